// round 1
// baseline (speedup 1.0000x reference)
#include <cuda_runtime.h>
#include <cuda_bf16.h>
#include <math.h>

// ---------------------------------------------------------------------------
// Problem constants
// ---------------------------------------------------------------------------
#define D_MODEL   256
#define DEPTH     2
#define D_INNER   512          // 2 * D_MODEL
#define D_STATE   16
#define D_CONV    4
#define DT_RANK   16           // (256+15)/16
#define BATCH     2
#define SEQLEN    2048
#define NTOK      (BATCH * SEQLEN)   // 4096
#define DBL_COLS  (DT_RANK + 2 * D_STATE)  // 48

// ---------------------------------------------------------------------------
// Scratch (device globals; no allocations allowed)
// ---------------------------------------------------------------------------
__device__ float g_h    [NTOK * D_MODEL];        // LN output
__device__ float g_xz   [NTOK * 2 * D_INNER];    // in_proj output (xi | z)
__device__ float g_xc   [NTOK * D_INNER];        // conv+silu output
__device__ float g_dbl  [NTOK * DBL_COLS];       // x_proj output (dt | B | C)
__device__ float g_delta[NTOK * D_INNER];        // softplus(dt @ dpw^T + dpb)
__device__ float g_y    [NTOK * D_INNER];        // scan output, then gated

// ---------------------------------------------------------------------------
// LayerNorm: one block per token, 256 threads
// ---------------------------------------------------------------------------
__global__ void ln_kernel(const float* __restrict__ x,
                          const float* __restrict__ w,
                          const float* __restrict__ b,
                          float* __restrict__ out)
{
    __shared__ float s_sum[8], s_sq[8];
    int t = blockIdx.x;
    int d = threadIdx.x;
    float v = x[t * D_MODEL + d];

    float s = v, q = v * v;
    #pragma unroll
    for (int o = 16; o > 0; o >>= 1) {
        s += __shfl_xor_sync(0xffffffffu, s, o);
        q += __shfl_xor_sync(0xffffffffu, q, o);
    }
    int warp = threadIdx.x >> 5;
    if ((threadIdx.x & 31) == 0) { s_sum[warp] = s; s_sq[warp] = q; }
    __syncthreads();
    if (threadIdx.x < 8) { s = s_sum[threadIdx.x]; q = s_sq[threadIdx.x]; }
    else                 { s = 0.f; q = 0.f; }
    if (warp == 0) {
        #pragma unroll
        for (int o = 4; o > 0; o >>= 1) {
            s += __shfl_xor_sync(0xffffffffu, s, o);
            q += __shfl_xor_sync(0xffffffffu, q, o);
        }
        if (threadIdx.x == 0) { s_sum[0] = s; s_sq[0] = q; }
    }
    __syncthreads();
    float mu  = s_sum[0] * (1.f / D_MODEL);
    float var = s_sq[0] * (1.f / D_MODEL) - mu * mu;
    float inv = rsqrtf(var + 1e-5f);
    out[t * D_MODEL + d] = (v - mu) * inv * w[d] + b[d];
}

// ---------------------------------------------------------------------------
// Generic tiled SGEMM: C[M,N] = A[M,K] * W[N,K]^T  (+ epilogue)
//   MODE 0: plain store
//   MODE 1: softplus(acc + bias[n])
//   MODE 2: residual: C[m,n] += acc
// BM=BN=64, BK=16, 256 threads, 4x4 per thread. M % 64 == 0, K % 16 == 0.
// ---------------------------------------------------------------------------
template <int MODE>
__global__ void sgemm_nt(const float* __restrict__ A, int lda,
                         const float* __restrict__ W, int ldw,
                         float*       __restrict__ C, int ldc,
                         int N, int K,
                         const float* __restrict__ bias)
{
    const int BM = 64, BN = 64, BK = 16;
    __shared__ float As[BM][BK + 1];
    __shared__ float Ws[BN][BK + 1];

    int tid = threadIdx.x;
    int m0 = blockIdx.y * BM;
    int n0 = blockIdx.x * BN;
    int lk = tid & 15;     // k-col for loads
    int lr = tid >> 4;     // base row for loads (0..15)
    int tx = tid & 15;     // col group for compute
    int ty = tid >> 4;     // row group for compute

    float acc[4][4];
    #pragma unroll
    for (int i = 0; i < 4; i++)
        #pragma unroll
        for (int j = 0; j < 4; j++) acc[i][j] = 0.f;

    for (int k0 = 0; k0 < K; k0 += BK) {
        #pragma unroll
        for (int i = 0; i < 4; i++) {
            int r = lr + 16 * i;
            As[r][lk] = A[(size_t)(m0 + r) * lda + k0 + lk];
        }
        #pragma unroll
        for (int i = 0; i < 4; i++) {
            int r = lr + 16 * i;
            int n = n0 + r;
            Ws[r][lk] = (n < N) ? W[(size_t)n * ldw + k0 + lk] : 0.f;
        }
        __syncthreads();
        #pragma unroll
        for (int kk = 0; kk < BK; kk++) {
            float a[4], w[4];
            #pragma unroll
            for (int i = 0; i < 4; i++) a[i] = As[ty + 16 * i][kk];
            #pragma unroll
            for (int j = 0; j < 4; j++) w[j] = Ws[tx + 16 * j][kk];
            #pragma unroll
            for (int i = 0; i < 4; i++)
                #pragma unroll
                for (int j = 0; j < 4; j++) acc[i][j] += a[i] * w[j];
        }
        __syncthreads();
    }

    #pragma unroll
    for (int i = 0; i < 4; i++) {
        int m = m0 + ty + 16 * i;
        #pragma unroll
        for (int j = 0; j < 4; j++) {
            int n = n0 + tx + 16 * j;
            if (n < N) {
                float v = acc[i][j];
                if (MODE == 1) {
                    v += bias[n];
                    v = (v > 20.f) ? v : log1pf(__expf(v));
                } else if (MODE == 2) {
                    v += C[(size_t)m * ldc + n];
                }
                C[(size_t)m * ldc + n] = v;
            }
        }
    }
}

// ---------------------------------------------------------------------------
// Depthwise causal conv (D_CONV=4) + SiLU.  xi lives in g_xz[:, 0:512].
// ---------------------------------------------------------------------------
__global__ void conv_silu_kernel(const float* __restrict__ xz,
                                 const float* __restrict__ cw,
                                 const float* __restrict__ cb,
                                 float* __restrict__ xc)
{
    int idx = blockIdx.x * blockDim.x + threadIdx.x;   // over NTOK * D_INNER
    if (idx >= NTOK * D_INNER) return;
    int d = idx & (D_INNER - 1);
    int t = idx >> 9;
    int l = t & (SEQLEN - 1);

    float acc = cb[d];
    #pragma unroll
    for (int k = 0; k < D_CONV; k++) {
        int ll = l - (D_CONV - 1) + k;
        if (ll >= 0)
            acc += xz[(size_t)(t - (D_CONV - 1) + k) * (2 * D_INNER) + d] * cw[d * D_CONV + k];
    }
    float sg = 1.f / (1.f + __expf(-acc));
    xc[idx] = acc * sg;
}

// ---------------------------------------------------------------------------
// Selective scan.  Grid: BATCH * (D_INNER/16) = 64 blocks of 256 threads.
// Thread = (d_local 0..15, n 0..15); 16 states reduced via shfl.
// ---------------------------------------------------------------------------
__global__ void scan_kernel(const float* __restrict__ delta,
                            const float* __restrict__ dbl,
                            const float* __restrict__ xc,
                            const float* __restrict__ A_log,
                            float* __restrict__ y)
{
    int b  = blockIdx.x >> 5;
    int dg = blockIdx.x & 31;
    int n  = threadIdx.x & 15;
    int dl = threadIdx.x >> 4;
    int d  = dg * 16 + dl;

    float Adn = -__expf(A_log[d * D_STATE + n]);
    float h = 0.f;

    const float* dptr = delta + (size_t)b * SEQLEN * D_INNER + d;
    const float* xptr = xc    + (size_t)b * SEQLEN * D_INNER + d;
    const float* Bptr = dbl   + (size_t)b * SEQLEN * DBL_COLS + DT_RANK + n;
    const float* Cptr = dbl   + (size_t)b * SEQLEN * DBL_COLS + DT_RANK + D_STATE + n;
    float*       yptr = y     + (size_t)b * SEQLEN * D_INNER + d;

    float dv = dptr[0], xv = xptr[0], Bv = Bptr[0], Cv = Cptr[0];
    for (int l = 0; l < SEQLEN; l++) {
        float dv_n = 0.f, xv_n = 0.f, Bv_n = 0.f, Cv_n = 0.f;
        if (l + 1 < SEQLEN) {
            dv_n = dptr[(l + 1) * D_INNER];
            xv_n = xptr[(l + 1) * D_INNER];
            Bv_n = Bptr[(l + 1) * DBL_COLS];
            Cv_n = Cptr[(l + 1) * DBL_COLS];
        }
        h = __expf(dv * Adn) * h + (dv * xv) * Bv;
        float p = h * Cv;
        p += __shfl_xor_sync(0xffffffffu, p, 8);
        p += __shfl_xor_sync(0xffffffffu, p, 4);
        p += __shfl_xor_sync(0xffffffffu, p, 2);
        p += __shfl_xor_sync(0xffffffffu, p, 1);
        if (n == 0) yptr[(size_t)l * D_INNER] = p;
        dv = dv_n; xv = xv_n; Bv = Bv_n; Cv = Cv_n;
    }
}

// ---------------------------------------------------------------------------
// Gate: y = (y + xc * D[d]) * silu(z)
// ---------------------------------------------------------------------------
__global__ void gate_kernel(float* __restrict__ y,
                            const float* __restrict__ xc,
                            const float* __restrict__ xz,
                            const float* __restrict__ Dp)
{
    int idx = blockIdx.x * blockDim.x + threadIdx.x;
    if (idx >= NTOK * D_INNER) return;
    int d = idx & (D_INNER - 1);
    int t = idx >> 9;
    float z = xz[(size_t)t * (2 * D_INNER) + D_INNER + d];
    float sz = z / (1.f + __expf(-z));
    y[idx] = (y[idx] + xc[idx] * Dp[d]) * sz;
}

// ---------------------------------------------------------------------------
// Launcher
// ---------------------------------------------------------------------------
extern "C" void kernel_launch(void* const* d_in, const int* in_sizes, int n_in,
                              void* d_out, int out_size)
{
    const float* x_in   = (const float*)d_in[0];
    const float* ln_w   = (const float*)d_in[1];
    const float* ln_b   = (const float*)d_in[2];
    const float* ipw    = (const float*)d_in[3];
    const float* cw     = (const float*)d_in[4];
    const float* cb     = (const float*)d_in[5];
    const float* xpw    = (const float*)d_in[6];
    const float* dpw    = (const float*)d_in[7];
    const float* dpb    = (const float*)d_in[8];
    const float* alog   = (const float*)d_in[9];
    const float* dpar   = (const float*)d_in[10];
    const float* opw    = (const float*)d_in[11];
    float* xbuf = (float*)d_out;   // residual stream lives in d_out

    float *p_h, *p_xz, *p_xc, *p_dbl, *p_delta, *p_y;
    cudaGetSymbolAddress((void**)&p_h,     g_h);
    cudaGetSymbolAddress((void**)&p_xz,    g_xz);
    cudaGetSymbolAddress((void**)&p_xc,    g_xc);
    cudaGetSymbolAddress((void**)&p_dbl,   g_dbl);
    cudaGetSymbolAddress((void**)&p_delta, g_delta);
    cudaGetSymbolAddress((void**)&p_y,     g_y);

    // x -> d_out (residual stream)
    cudaMemcpyAsync(xbuf, x_in, (size_t)NTOK * D_MODEL * sizeof(float),
                    cudaMemcpyDeviceToDevice);

    const int EW_THREADS = 256;
    const int EW_BLOCKS  = (NTOK * D_INNER + EW_THREADS - 1) / EW_THREADS;

    for (int layer = 0; layer < DEPTH; layer++) {
        const float* l_lnw  = ln_w + layer * D_MODEL;
        const float* l_lnb  = ln_b + layer * D_MODEL;
        const float* l_ipw  = ipw  + (size_t)layer * 2 * D_INNER * D_MODEL;
        const float* l_cw   = cw   + (size_t)layer * D_INNER * D_CONV;
        const float* l_cb   = cb   + (size_t)layer * D_INNER;
        const float* l_xpw  = xpw  + (size_t)layer * DBL_COLS * D_INNER;
        const float* l_dpw  = dpw  + (size_t)layer * D_INNER * DT_RANK;
        const float* l_dpb  = dpb  + (size_t)layer * D_INNER;
        const float* l_alog = alog + (size_t)layer * D_INNER * D_STATE;
        const float* l_dpar = dpar + (size_t)layer * D_INNER;
        const float* l_opw  = opw  + (size_t)layer * D_MODEL * D_INNER;

        // 1. LayerNorm
        ln_kernel<<<NTOK, D_MODEL>>>(xbuf, l_lnw, l_lnb, p_h);

        // 2. in_proj: g_xz[4096,1024] = g_h[4096,256] @ ipw[1024,256]^T
        sgemm_nt<0><<<dim3((2 * D_INNER + 63) / 64, NTOK / 64), 256>>>(
            p_h, D_MODEL, l_ipw, D_MODEL, p_xz, 2 * D_INNER,
            2 * D_INNER, D_MODEL, nullptr);

        // 3. depthwise conv + silu
        conv_silu_kernel<<<EW_BLOCKS, EW_THREADS>>>(p_xz, l_cw, l_cb, p_xc);

        // 4. x_proj: g_dbl[4096,48] = g_xc[4096,512] @ xpw[48,512]^T
        sgemm_nt<0><<<dim3(1, NTOK / 64), 256>>>(
            p_xc, D_INNER, l_xpw, D_INNER, p_dbl, DBL_COLS,
            DBL_COLS, D_INNER, nullptr);

        // 5. delta: softplus(g_dbl[:, :16] @ dpw[512,16]^T + dpb)
        sgemm_nt<1><<<dim3((D_INNER + 63) / 64, NTOK / 64), 256>>>(
            p_dbl, DBL_COLS, l_dpw, DT_RANK, p_delta, D_INNER,
            D_INNER, DT_RANK, l_dpb);

        // 6. selective scan
        scan_kernel<<<BATCH * (D_INNER / 16), 256>>>(
            p_delta, p_dbl, p_xc, l_alog, p_y);

        // 7. gate: y = (y + xc*D) * silu(z)
        gate_kernel<<<EW_BLOCKS, EW_THREADS>>>(p_y, p_xc, p_xz, l_dpar);

        // 8. out_proj + residual: xbuf += g_y @ opw[256,512]^T
        sgemm_nt<2><<<dim3((D_MODEL + 63) / 64, NTOK / 64), 256>>>(
            p_y, D_INNER, l_opw, D_INNER, xbuf, D_MODEL,
            D_MODEL, D_INNER, nullptr);
    }
}

// round 2
// speedup vs baseline: 1.0087x; 1.0087x over previous
#include <cuda_runtime.h>
#include <cuda_bf16.h>
#include <math.h>
#include <stdint.h>

// ---------------------------------------------------------------------------
// Problem constants
// ---------------------------------------------------------------------------
#define D_MODEL   256
#define DEPTH     2
#define D_INNER   512
#define D_STATE   16
#define D_CONV    4
#define DT_RANK   16
#define BATCH     2
#define SEQLEN    2048
#define NTOK      (BATCH * SEQLEN)          // 4096
#define DBL_COLS  (DT_RANK + 2 * D_STATE)   // 48

// ---------------------------------------------------------------------------
// Scratch (device globals; no allocations allowed)
// ---------------------------------------------------------------------------
__device__ float g_h    [NTOK * D_MODEL];
__device__ float g_xz   [NTOK * 2 * D_INNER];
__device__ float g_xc   [NTOK * D_INNER];
__device__ float g_dbl  [NTOK * DBL_COLS];
__device__ float g_delta[NTOK * D_INNER];
__device__ float g_y    [NTOK * D_INNER];

__device__ __forceinline__ uint32_t f2tf32(float f) {
    uint32_t u;
    asm("cvt.rna.tf32.f32 %0, %1;" : "=r"(u) : "f"(f));
    return u;
}

// ---------------------------------------------------------------------------
// LayerNorm: one block per token, 256 threads
// ---------------------------------------------------------------------------
__global__ void ln_kernel(const float* __restrict__ x,
                          const float* __restrict__ w,
                          const float* __restrict__ b,
                          float* __restrict__ out)
{
    __shared__ float s_sum[8], s_sq[8];
    int t = blockIdx.x;
    int d = threadIdx.x;
    float v = x[t * D_MODEL + d];

    float s = v, q = v * v;
    #pragma unroll
    for (int o = 16; o > 0; o >>= 1) {
        s += __shfl_xor_sync(0xffffffffu, s, o);
        q += __shfl_xor_sync(0xffffffffu, q, o);
    }
    int warp = threadIdx.x >> 5;
    if ((threadIdx.x & 31) == 0) { s_sum[warp] = s; s_sq[warp] = q; }
    __syncthreads();
    if (threadIdx.x < 8) { s = s_sum[threadIdx.x]; q = s_sq[threadIdx.x]; }
    else                 { s = 0.f; q = 0.f; }
    if (warp == 0) {
        #pragma unroll
        for (int o = 4; o > 0; o >>= 1) {
            s += __shfl_xor_sync(0xffffffffu, s, o);
            q += __shfl_xor_sync(0xffffffffu, q, o);
        }
        if (threadIdx.x == 0) { s_sum[0] = s; s_sq[0] = q; }
    }
    __syncthreads();
    float mu  = s_sum[0] * (1.f / D_MODEL);
    float var = s_sq[0] * (1.f / D_MODEL) - mu * mu;
    float inv = rsqrtf(var + 1e-5f);
    out[t * D_MODEL + d] = (v - mu) * inv * w[d] + b[d];
}

// ---------------------------------------------------------------------------
// tf32 tensor-core GEMM: C[M,N] = A[M,K] @ W[N,K]^T  (+ epilogue)
//   MODE 0: plain store
//   MODE 1: softplus(acc + bias[n])
//   MODE 2: residual: C[m,n] += acc
// BM=128, BN=64, BK=16. 256 threads = 8 warps (4 M x 2 N), 32x32 warp tile,
// mma.sync.m16n8k8 tf32. Requires M%128==0, K%16==0, A/W 16B-aligned rows
// (lda, ldw multiples of 4). N handled with guards.
// ---------------------------------------------------------------------------
template <int MODE>
__global__ __launch_bounds__(256)
void gemm_tf32(const float* __restrict__ A, int lda,
               const float* __restrict__ W, int ldw,
               float*       __restrict__ C, int ldc,
               int N, int K,
               const float* __restrict__ bias)
{
    const int BM = 128, BN = 64, BK = 16, LDS = 20;   // stride 20: conflict-free
    __shared__ uint32_t As[BM * LDS];
    __shared__ uint32_t Bs[BN * LDS];

    int tid  = threadIdx.x;
    int lane = tid & 31;
    int warp = tid >> 5;
    int m0 = blockIdx.y * BM;
    int n0 = blockIdx.x * BN;
    int wm = (warp >> 1) * 32;     // warp tile m-offset
    int wn = (warp & 1) * 32;      // warp tile n-offset
    int gr = lane >> 2;            // 0..7
    int gc = lane & 3;             // 0..3

    float acc[2][4][4];
    #pragma unroll
    for (int mi = 0; mi < 2; mi++)
        #pragma unroll
        for (int ni = 0; ni < 4; ni++)
            #pragma unroll
            for (int e = 0; e < 4; e++) acc[mi][ni][e] = 0.f;

    int lrow = tid >> 2;           // 0..63
    int lcol = (tid & 3) * 4;      // 0,4,8,12

    for (int k0 = 0; k0 < K; k0 += BK) {
        // A tile: 128 rows x 16 cols
        #pragma unroll
        for (int h = 0; h < 2; h++) {
            int r = lrow + h * 64;
            float4 v = *(const float4*)&A[(size_t)(m0 + r) * lda + k0 + lcol];
            As[r * LDS + lcol + 0] = f2tf32(v.x);
            As[r * LDS + lcol + 1] = f2tf32(v.y);
            As[r * LDS + lcol + 2] = f2tf32(v.z);
            As[r * LDS + lcol + 3] = f2tf32(v.w);
        }
        // W tile: 64 rows x 16 cols (guarded on N)
        {
            int r = lrow;
            float4 v = make_float4(0.f, 0.f, 0.f, 0.f);
            if (n0 + r < N)
                v = *(const float4*)&W[(size_t)(n0 + r) * ldw + k0 + lcol];
            Bs[r * LDS + lcol + 0] = f2tf32(v.x);
            Bs[r * LDS + lcol + 1] = f2tf32(v.y);
            Bs[r * LDS + lcol + 2] = f2tf32(v.z);
            Bs[r * LDS + lcol + 3] = f2tf32(v.w);
        }
        __syncthreads();

        #pragma unroll
        for (int ks = 0; ks < BK; ks += 8) {
            uint32_t a[2][4], b[4][2];
            #pragma unroll
            for (int mi = 0; mi < 2; mi++) {
                int rb = wm + mi * 16 + gr;
                a[mi][0] = As[rb * LDS + ks + gc];
                a[mi][1] = As[(rb + 8) * LDS + ks + gc];
                a[mi][2] = As[rb * LDS + ks + gc + 4];
                a[mi][3] = As[(rb + 8) * LDS + ks + gc + 4];
            }
            #pragma unroll
            for (int ni = 0; ni < 4; ni++) {
                int rb = wn + ni * 8 + gr;
                b[ni][0] = Bs[rb * LDS + ks + gc];
                b[ni][1] = Bs[rb * LDS + ks + gc + 4];
            }
            #pragma unroll
            for (int mi = 0; mi < 2; mi++)
                #pragma unroll
                for (int ni = 0; ni < 4; ni++)
                    asm volatile(
                        "mma.sync.aligned.m16n8k8.row.col.f32.tf32.tf32.f32 "
                        "{%0,%1,%2,%3}, {%4,%5,%6,%7}, {%8,%9}, {%0,%1,%2,%3};"
                        : "+f"(acc[mi][ni][0]), "+f"(acc[mi][ni][1]),
                          "+f"(acc[mi][ni][2]), "+f"(acc[mi][ni][3])
                        : "r"(a[mi][0]), "r"(a[mi][1]), "r"(a[mi][2]), "r"(a[mi][3]),
                          "r"(b[ni][0]), "r"(b[ni][1]));
        }
        __syncthreads();
    }

    // Epilogue
    #pragma unroll
    for (int mi = 0; mi < 2; mi++) {
        #pragma unroll
        for (int ni = 0; ni < 4; ni++) {
            #pragma unroll
            for (int e = 0; e < 4; e++) {
                int row = m0 + wm + mi * 16 + gr + ((e >= 2) ? 8 : 0);
                int col = n0 + wn + ni * 8 + gc * 2 + (e & 1);
                if (col < N) {
                    float v = acc[mi][ni][e];
                    if (MODE == 1) {
                        v += bias[col];
                        v = (v > 20.f) ? v : log1pf(__expf(v));
                    } else if (MODE == 2) {
                        v += C[(size_t)row * ldc + col];
                    }
                    C[(size_t)row * ldc + col] = v;
                }
            }
        }
    }
}

// ---------------------------------------------------------------------------
// Depthwise causal conv (D_CONV=4) + SiLU
// ---------------------------------------------------------------------------
__global__ void conv_silu_kernel(const float* __restrict__ xz,
                                 const float* __restrict__ cw,
                                 const float* __restrict__ cb,
                                 float* __restrict__ xc)
{
    int idx = blockIdx.x * blockDim.x + threadIdx.x;
    if (idx >= NTOK * D_INNER) return;
    int d = idx & (D_INNER - 1);
    int t = idx >> 9;
    int l = t & (SEQLEN - 1);

    float acc = cb[d];
    #pragma unroll
    for (int k = 0; k < D_CONV; k++) {
        int ll = l - (D_CONV - 1) + k;
        if (ll >= 0)
            acc += xz[(size_t)(t - (D_CONV - 1) + k) * (2 * D_INNER) + d] * cw[d * D_CONV + k];
    }
    float sg = 1.f / (1.f + __expf(-acc));
    xc[idx] = acc * sg;
}

// ---------------------------------------------------------------------------
// Selective scan + fused gate.
// Grid: BATCH * (D_INNER/16) = 64 blocks x 256 threads.
// Thread = (d_local 0..15, n 0..15); states reduced via shfl within 16 lanes.
// Writes y = (scan + xc*D) * silu(z) directly.
// ---------------------------------------------------------------------------
__global__ void scan_kernel(const float* __restrict__ delta,
                            const float* __restrict__ dbl,
                            const float* __restrict__ xc,
                            const float* __restrict__ xz,
                            const float* __restrict__ A_log,
                            const float* __restrict__ Dp,
                            float* __restrict__ y)
{
    int b  = blockIdx.x >> 5;
    int dg = blockIdx.x & 31;
    int n  = threadIdx.x & 15;
    int dl = threadIdx.x >> 4;
    int d  = dg * 16 + dl;

    float Adn = -__expf(A_log[d * D_STATE + n]);
    float Dd  = Dp[d];
    float h = 0.f;

    const float* dptr = delta + (size_t)b * SEQLEN * D_INNER + d;
    const float* xptr = xc    + (size_t)b * SEQLEN * D_INNER + d;
    const float* zptr = xz    + (size_t)b * SEQLEN * 2 * D_INNER + D_INNER + d;
    const float* Bptr = dbl   + (size_t)b * SEQLEN * DBL_COLS + DT_RANK + n;
    const float* Cptr = dbl   + (size_t)b * SEQLEN * DBL_COLS + DT_RANK + D_STATE + n;
    float*       yptr = y     + (size_t)b * SEQLEN * D_INNER + d;

    float dv = dptr[0], xv = xptr[0], Bv = Bptr[0], Cv = Cptr[0], zv = zptr[0];
    for (int l = 0; l < SEQLEN; l++) {
        float dv_n = 0.f, xv_n = 0.f, Bv_n = 0.f, Cv_n = 0.f, zv_n = 0.f;
        if (l + 1 < SEQLEN) {
            dv_n = dptr[(size_t)(l + 1) * D_INNER];
            xv_n = xptr[(size_t)(l + 1) * D_INNER];
            zv_n = zptr[(size_t)(l + 1) * 2 * D_INNER];
            Bv_n = Bptr[(size_t)(l + 1) * DBL_COLS];
            Cv_n = Cptr[(size_t)(l + 1) * DBL_COLS];
        }
        h = __expf(dv * Adn) * h + (dv * xv) * Bv;
        float p = h * Cv;
        p += __shfl_xor_sync(0xffffffffu, p, 8);
        p += __shfl_xor_sync(0xffffffffu, p, 4);
        p += __shfl_xor_sync(0xffffffffu, p, 2);
        p += __shfl_xor_sync(0xffffffffu, p, 1);
        if (n == 0) {
            float sz = zv / (1.f + __expf(-zv));
            yptr[(size_t)l * D_INNER] = (p + xv * Dd) * sz;
        }
        dv = dv_n; xv = xv_n; Bv = Bv_n; Cv = Cv_n; zv = zv_n;
    }
}

// ---------------------------------------------------------------------------
// Launcher
// ---------------------------------------------------------------------------
extern "C" void kernel_launch(void* const* d_in, const int* in_sizes, int n_in,
                              void* d_out, int out_size)
{
    const float* x_in = (const float*)d_in[0];
    const float* ln_w = (const float*)d_in[1];
    const float* ln_b = (const float*)d_in[2];
    const float* ipw  = (const float*)d_in[3];
    const float* cw   = (const float*)d_in[4];
    const float* cb   = (const float*)d_in[5];
    const float* xpw  = (const float*)d_in[6];
    const float* dpw  = (const float*)d_in[7];
    const float* dpb  = (const float*)d_in[8];
    const float* alog = (const float*)d_in[9];
    const float* dpar = (const float*)d_in[10];
    const float* opw  = (const float*)d_in[11];
    float* xbuf = (float*)d_out;

    float *p_h, *p_xz, *p_xc, *p_dbl, *p_delta, *p_y;
    cudaGetSymbolAddress((void**)&p_h,     g_h);
    cudaGetSymbolAddress((void**)&p_xz,    g_xz);
    cudaGetSymbolAddress((void**)&p_xc,    g_xc);
    cudaGetSymbolAddress((void**)&p_dbl,   g_dbl);
    cudaGetSymbolAddress((void**)&p_delta, g_delta);
    cudaGetSymbolAddress((void**)&p_y,     g_y);

    cudaMemcpyAsync(xbuf, x_in, (size_t)NTOK * D_MODEL * sizeof(float),
                    cudaMemcpyDeviceToDevice);

    const int EW_THREADS = 256;
    const int EW_BLOCKS  = (NTOK * D_INNER + EW_THREADS - 1) / EW_THREADS;

    for (int layer = 0; layer < DEPTH; layer++) {
        const float* l_lnw  = ln_w + layer * D_MODEL;
        const float* l_lnb  = ln_b + layer * D_MODEL;
        const float* l_ipw  = ipw  + (size_t)layer * 2 * D_INNER * D_MODEL;
        const float* l_cw   = cw   + (size_t)layer * D_INNER * D_CONV;
        const float* l_cb   = cb   + (size_t)layer * D_INNER;
        const float* l_xpw  = xpw  + (size_t)layer * DBL_COLS * D_INNER;
        const float* l_dpw  = dpw  + (size_t)layer * D_INNER * DT_RANK;
        const float* l_dpb  = dpb  + (size_t)layer * D_INNER;
        const float* l_alog = alog + (size_t)layer * D_INNER * D_STATE;
        const float* l_dpar = dpar + (size_t)layer * D_INNER;
        const float* l_opw  = opw  + (size_t)layer * D_MODEL * D_INNER;

        // 1. LayerNorm
        ln_kernel<<<NTOK, D_MODEL>>>(xbuf, l_lnw, l_lnb, p_h);

        // 2. in_proj: [4096,1024] = h[4096,256] @ ipw[1024,256]^T
        gemm_tf32<0><<<dim3((2 * D_INNER + 63) / 64, NTOK / 128), 256>>>(
            p_h, D_MODEL, l_ipw, D_MODEL, p_xz, 2 * D_INNER,
            2 * D_INNER, D_MODEL, nullptr);

        // 3. depthwise conv + silu
        conv_silu_kernel<<<EW_BLOCKS, EW_THREADS>>>(p_xz, l_cw, l_cb, p_xc);

        // 4. x_proj: [4096,48] = xc[4096,512] @ xpw[48,512]^T
        gemm_tf32<0><<<dim3(1, NTOK / 128), 256>>>(
            p_xc, D_INNER, l_xpw, D_INNER, p_dbl, DBL_COLS,
            DBL_COLS, D_INNER, nullptr);

        // 5. delta: softplus(dbl[:, :16] @ dpw[512,16]^T + dpb)
        gemm_tf32<1><<<dim3((D_INNER + 63) / 64, NTOK / 128), 256>>>(
            p_dbl, DBL_COLS, l_dpw, DT_RANK, p_delta, D_INNER,
            D_INNER, DT_RANK, l_dpb);

        // 6. selective scan + gate
        scan_kernel<<<BATCH * (D_INNER / 16), 256>>>(
            p_delta, p_dbl, p_xc, p_xz, l_alog, l_dpar, p_y);

        // 7. out_proj + residual: xbuf += y @ opw[256,512]^T
        gemm_tf32<2><<<dim3((D_MODEL + 63) / 64, NTOK / 128), 256>>>(
            p_y, D_INNER, l_opw, D_INNER, xbuf, D_MODEL,
            D_MODEL, D_INNER, nullptr);
    }
}

// round 3
// speedup vs baseline: 3.6449x; 3.6134x over previous
#include <cuda_runtime.h>
#include <cuda_bf16.h>
#include <math.h>
#include <stdint.h>

// ---------------------------------------------------------------------------
// Problem constants
// ---------------------------------------------------------------------------
#define D_MODEL   256
#define DEPTH     2
#define D_INNER   512
#define D_STATE   16
#define D_CONV    4
#define DT_RANK   16
#define BATCH     2
#define SEQLEN    2048
#define NTOK      (BATCH * SEQLEN)          // 4096
#define DBL_COLS  (DT_RANK + 2 * D_STATE)   // 48

#define NCHUNK    32
#define CLEN      (SEQLEN / NCHUNK)         // 64

// ---------------------------------------------------------------------------
// Scratch (device globals; no allocations allowed)
// ---------------------------------------------------------------------------
__device__ float g_h    [NTOK * D_MODEL];
__device__ float g_xz   [NTOK * 2 * D_INNER];
__device__ float g_xc   [NTOK * D_INNER];
__device__ float g_dbl  [NTOK * DBL_COLS];
__device__ float g_delta[NTOK * D_INNER];
__device__ float g_y    [NTOK * D_INNER];
__device__ float g_cA   [BATCH * NCHUNK * D_INNER * D_STATE];  // chunk a-product
__device__ float g_cH   [BATCH * NCHUNK * D_INNER * D_STATE];  // chunk end-state (h0=0)
__device__ float g_hs   [BATCH * NCHUNK * D_INNER * D_STATE];  // chunk start-state

__device__ __forceinline__ uint32_t f2tf32(float f) {
    uint32_t u;
    asm("cvt.rna.tf32.f32 %0, %1;" : "=r"(u) : "f"(f));
    return u;
}

// ---------------------------------------------------------------------------
// LayerNorm: one block per token, 256 threads
// ---------------------------------------------------------------------------
__global__ void ln_kernel(const float* __restrict__ x,
                          const float* __restrict__ w,
                          const float* __restrict__ b,
                          float* __restrict__ out)
{
    __shared__ float s_sum[8], s_sq[8];
    int t = blockIdx.x;
    int d = threadIdx.x;
    float v = x[t * D_MODEL + d];

    float s = v, q = v * v;
    #pragma unroll
    for (int o = 16; o > 0; o >>= 1) {
        s += __shfl_xor_sync(0xffffffffu, s, o);
        q += __shfl_xor_sync(0xffffffffu, q, o);
    }
    int warp = threadIdx.x >> 5;
    if ((threadIdx.x & 31) == 0) { s_sum[warp] = s; s_sq[warp] = q; }
    __syncthreads();
    if (threadIdx.x < 8) { s = s_sum[threadIdx.x]; q = s_sq[threadIdx.x]; }
    else                 { s = 0.f; q = 0.f; }
    if (warp == 0) {
        #pragma unroll
        for (int o = 4; o > 0; o >>= 1) {
            s += __shfl_xor_sync(0xffffffffu, s, o);
            q += __shfl_xor_sync(0xffffffffu, q, o);
        }
        if (threadIdx.x == 0) { s_sum[0] = s; s_sq[0] = q; }
    }
    __syncthreads();
    float mu  = s_sum[0] * (1.f / D_MODEL);
    float var = s_sq[0] * (1.f / D_MODEL) - mu * mu;
    float inv = rsqrtf(var + 1e-5f);
    out[t * D_MODEL + d] = (v - mu) * inv * w[d] + b[d];
}

// ---------------------------------------------------------------------------
// tf32 tensor-core GEMM: C[M,N] = A[M,K] @ W[N,K]^T  (+ epilogue)
//   MODE 0: plain store | MODE 1: softplus(acc+bias[n]) | MODE 2: C += acc
// BM=128, BN=64, BK=16, 256 threads = 8 warps (4x2), mma.m16n8k8 tf32.
// ---------------------------------------------------------------------------
template <int MODE>
__global__ __launch_bounds__(256)
void gemm_tf32(const float* __restrict__ A, int lda,
               const float* __restrict__ W, int ldw,
               float*       __restrict__ C, int ldc,
               int N, int K,
               const float* __restrict__ bias)
{
    const int BM = 128, BN = 64, BK = 16, LDS = 20;
    __shared__ uint32_t As[BM * LDS];
    __shared__ uint32_t Bs[BN * LDS];

    int tid  = threadIdx.x;
    int lane = tid & 31;
    int warp = tid >> 5;
    int m0 = blockIdx.y * BM;
    int n0 = blockIdx.x * BN;
    int wm = (warp >> 1) * 32;
    int wn = (warp & 1) * 32;
    int gr = lane >> 2;
    int gc = lane & 3;

    float acc[2][4][4];
    #pragma unroll
    for (int mi = 0; mi < 2; mi++)
        #pragma unroll
        for (int ni = 0; ni < 4; ni++)
            #pragma unroll
            for (int e = 0; e < 4; e++) acc[mi][ni][e] = 0.f;

    int lrow = tid >> 2;
    int lcol = (tid & 3) * 4;

    for (int k0 = 0; k0 < K; k0 += BK) {
        #pragma unroll
        for (int h = 0; h < 2; h++) {
            int r = lrow + h * 64;
            float4 v = *(const float4*)&A[(size_t)(m0 + r) * lda + k0 + lcol];
            As[r * LDS + lcol + 0] = f2tf32(v.x);
            As[r * LDS + lcol + 1] = f2tf32(v.y);
            As[r * LDS + lcol + 2] = f2tf32(v.z);
            As[r * LDS + lcol + 3] = f2tf32(v.w);
        }
        {
            int r = lrow;
            float4 v = make_float4(0.f, 0.f, 0.f, 0.f);
            if (n0 + r < N)
                v = *(const float4*)&W[(size_t)(n0 + r) * ldw + k0 + lcol];
            Bs[r * LDS + lcol + 0] = f2tf32(v.x);
            Bs[r * LDS + lcol + 1] = f2tf32(v.y);
            Bs[r * LDS + lcol + 2] = f2tf32(v.z);
            Bs[r * LDS + lcol + 3] = f2tf32(v.w);
        }
        __syncthreads();

        #pragma unroll
        for (int ks = 0; ks < BK; ks += 8) {
            uint32_t a[2][4], b[4][2];
            #pragma unroll
            for (int mi = 0; mi < 2; mi++) {
                int rb = wm + mi * 16 + gr;
                a[mi][0] = As[rb * LDS + ks + gc];
                a[mi][1] = As[(rb + 8) * LDS + ks + gc];
                a[mi][2] = As[rb * LDS + ks + gc + 4];
                a[mi][3] = As[(rb + 8) * LDS + ks + gc + 4];
            }
            #pragma unroll
            for (int ni = 0; ni < 4; ni++) {
                int rb = wn + ni * 8 + gr;
                b[ni][0] = Bs[rb * LDS + ks + gc];
                b[ni][1] = Bs[rb * LDS + ks + gc + 4];
            }
            #pragma unroll
            for (int mi = 0; mi < 2; mi++)
                #pragma unroll
                for (int ni = 0; ni < 4; ni++)
                    asm volatile(
                        "mma.sync.aligned.m16n8k8.row.col.f32.tf32.tf32.f32 "
                        "{%0,%1,%2,%3}, {%4,%5,%6,%7}, {%8,%9}, {%0,%1,%2,%3};"
                        : "+f"(acc[mi][ni][0]), "+f"(acc[mi][ni][1]),
                          "+f"(acc[mi][ni][2]), "+f"(acc[mi][ni][3])
                        : "r"(a[mi][0]), "r"(a[mi][1]), "r"(a[mi][2]), "r"(a[mi][3]),
                          "r"(b[ni][0]), "r"(b[ni][1]));
        }
        __syncthreads();
    }

    #pragma unroll
    for (int mi = 0; mi < 2; mi++) {
        #pragma unroll
        for (int ni = 0; ni < 4; ni++) {
            #pragma unroll
            for (int e = 0; e < 4; e++) {
                int row = m0 + wm + mi * 16 + gr + ((e >= 2) ? 8 : 0);
                int col = n0 + wn + ni * 8 + gc * 2 + (e & 1);
                if (col < N) {
                    float v = acc[mi][ni][e];
                    if (MODE == 1) {
                        v += bias[col];
                        v = (v > 20.f) ? v : log1pf(__expf(v));
                    } else if (MODE == 2) {
                        v += C[(size_t)row * ldc + col];
                    }
                    C[(size_t)row * ldc + col] = v;
                }
            }
        }
    }
}

// ---------------------------------------------------------------------------
// Depthwise causal conv (D_CONV=4) + SiLU
// ---------------------------------------------------------------------------
__global__ void conv_silu_kernel(const float* __restrict__ xz,
                                 const float* __restrict__ cw,
                                 const float* __restrict__ cb,
                                 float* __restrict__ xc)
{
    int idx = blockIdx.x * blockDim.x + threadIdx.x;
    if (idx >= NTOK * D_INNER) return;
    int d = idx & (D_INNER - 1);
    int t = idx >> 9;
    int l = t & (SEQLEN - 1);

    float acc = cb[d];
    #pragma unroll
    for (int k = 0; k < D_CONV; k++) {
        int ll = l - (D_CONV - 1) + k;
        if (ll >= 0)
            acc += xz[(size_t)(t - (D_CONV - 1) + k) * (2 * D_INNER) + d] * cw[d * D_CONV + k];
    }
    float sg = 1.f / (1.f + __expf(-acc));
    xc[idx] = acc * sg;
}

// ---------------------------------------------------------------------------
// Chunked selective scan.
// Grid for S1/S3: BATCH * NCHUNK * 32  (block = 16 d x 16 n = 256 threads)
//   blockIdx.x = b*(NCHUNK*32) + c*32 + dg
// ---------------------------------------------------------------------------
__global__ void scan_part1(const float* __restrict__ delta,
                           const float* __restrict__ dbl,
                           const float* __restrict__ xc,
                           const float* __restrict__ A_log,
                           float* __restrict__ cA,
                           float* __restrict__ cH)
{
    int dg = blockIdx.x & 31;
    int c  = (blockIdx.x >> 5) & (NCHUNK - 1);
    int b  = blockIdx.x >> 10;
    int n  = threadIdx.x & 15;
    int dl = threadIdx.x >> 4;
    int d  = dg * 16 + dl;

    float Adn = -__expf(A_log[d * D_STATE + n]);
    int l0 = c * CLEN;
    const float* dptr = delta + ((size_t)b * SEQLEN + l0) * D_INNER + d;
    const float* xptr = xc    + ((size_t)b * SEQLEN + l0) * D_INNER + d;
    const float* Bptr = dbl   + ((size_t)b * SEQLEN + l0) * DBL_COLS + DT_RANK + n;

    float h = 0.f, P = 1.f;
    float dv = dptr[0], xv = xptr[0], Bv = Bptr[0];
    #pragma unroll 4
    for (int l = 0; l < CLEN; l++) {
        float dv_n = 0.f, xv_n = 0.f, Bv_n = 0.f;
        if (l + 1 < CLEN) {
            dv_n = dptr[(size_t)(l + 1) * D_INNER];
            xv_n = xptr[(size_t)(l + 1) * D_INNER];
            Bv_n = Bptr[(size_t)(l + 1) * DBL_COLS];
        }
        float a = __expf(dv * Adn);
        h = a * h + (dv * xv) * Bv;
        P *= a;
        dv = dv_n; xv = xv_n; Bv = Bv_n;
    }
    size_t o = (((size_t)b * NCHUNK + c) * D_INNER + d) * D_STATE + n;
    cA[o] = P;
    cH[o] = h;
}

__global__ void scan_part2(const float* __restrict__ cA,
                           const float* __restrict__ cH,
                           float* __restrict__ hs)
{
    int idx = blockIdx.x * blockDim.x + threadIdx.x;  // B*D_INNER*D_STATE = 16384
    if (idx >= BATCH * D_INNER * D_STATE) return;
    int b = idx / (D_INNER * D_STATE);
    int r = idx % (D_INNER * D_STATE);
    float h = 0.f;
    #pragma unroll
    for (int c = 0; c < NCHUNK; c++) {
        size_t o = ((size_t)(b * NCHUNK + c)) * (D_INNER * D_STATE) + r;
        hs[o] = h;
        h = cA[o] * h + cH[o];
    }
}

__global__ void scan_part3(const float* __restrict__ delta,
                           const float* __restrict__ dbl,
                           const float* __restrict__ xc,
                           const float* __restrict__ xz,
                           const float* __restrict__ A_log,
                           const float* __restrict__ Dp,
                           const float* __restrict__ hs,
                           float* __restrict__ y)
{
    int dg = blockIdx.x & 31;
    int c  = (blockIdx.x >> 5) & (NCHUNK - 1);
    int b  = blockIdx.x >> 10;
    int n  = threadIdx.x & 15;
    int dl = threadIdx.x >> 4;
    int d  = dg * 16 + dl;

    float Adn = -__expf(A_log[d * D_STATE + n]);
    float Dd  = Dp[d];
    int l0 = c * CLEN;
    const float* dptr = delta + ((size_t)b * SEQLEN + l0) * D_INNER + d;
    const float* xptr = xc    + ((size_t)b * SEQLEN + l0) * D_INNER + d;
    const float* zptr = xz    + ((size_t)b * SEQLEN + l0) * 2 * D_INNER + D_INNER + d;
    const float* Bptr = dbl   + ((size_t)b * SEQLEN + l0) * DBL_COLS + DT_RANK + n;
    const float* Cptr = dbl   + ((size_t)b * SEQLEN + l0) * DBL_COLS + DT_RANK + D_STATE + n;
    float*       yptr = y     + ((size_t)b * SEQLEN + l0) * D_INNER + d;

    float h = hs[(((size_t)b * NCHUNK + c) * D_INNER + d) * D_STATE + n];

    float dv = dptr[0], xv = xptr[0], Bv = Bptr[0], Cv = Cptr[0], zv = zptr[0];
    #pragma unroll 2
    for (int l = 0; l < CLEN; l++) {
        float dv_n = 0.f, xv_n = 0.f, Bv_n = 0.f, Cv_n = 0.f, zv_n = 0.f;
        if (l + 1 < CLEN) {
            dv_n = dptr[(size_t)(l + 1) * D_INNER];
            xv_n = xptr[(size_t)(l + 1) * D_INNER];
            zv_n = zptr[(size_t)(l + 1) * 2 * D_INNER];
            Bv_n = Bptr[(size_t)(l + 1) * DBL_COLS];
            Cv_n = Cptr[(size_t)(l + 1) * DBL_COLS];
        }
        h = __expf(dv * Adn) * h + (dv * xv) * Bv;
        float p = h * Cv;
        p += __shfl_xor_sync(0xffffffffu, p, 8);
        p += __shfl_xor_sync(0xffffffffu, p, 4);
        p += __shfl_xor_sync(0xffffffffu, p, 2);
        p += __shfl_xor_sync(0xffffffffu, p, 1);
        if (n == 0) {
            float sz = zv / (1.f + __expf(-zv));
            yptr[(size_t)l * D_INNER] = (p + xv * Dd) * sz;
        }
        dv = dv_n; xv = xv_n; Bv = Bv_n; Cv = Cv_n; zv = zv_n;
    }
}

// ---------------------------------------------------------------------------
// Launcher
// ---------------------------------------------------------------------------
extern "C" void kernel_launch(void* const* d_in, const int* in_sizes, int n_in,
                              void* d_out, int out_size)
{
    const float* x_in = (const float*)d_in[0];
    const float* ln_w = (const float*)d_in[1];
    const float* ln_b = (const float*)d_in[2];
    const float* ipw  = (const float*)d_in[3];
    const float* cw   = (const float*)d_in[4];
    const float* cb   = (const float*)d_in[5];
    const float* xpw  = (const float*)d_in[6];
    const float* dpw  = (const float*)d_in[7];
    const float* dpb  = (const float*)d_in[8];
    const float* alog = (const float*)d_in[9];
    const float* dpar = (const float*)d_in[10];
    const float* opw  = (const float*)d_in[11];
    float* xbuf = (float*)d_out;

    float *p_h, *p_xz, *p_xc, *p_dbl, *p_delta, *p_y, *p_cA, *p_cH, *p_hs;
    cudaGetSymbolAddress((void**)&p_h,     g_h);
    cudaGetSymbolAddress((void**)&p_xz,    g_xz);
    cudaGetSymbolAddress((void**)&p_xc,    g_xc);
    cudaGetSymbolAddress((void**)&p_dbl,   g_dbl);
    cudaGetSymbolAddress((void**)&p_delta, g_delta);
    cudaGetSymbolAddress((void**)&p_y,     g_y);
    cudaGetSymbolAddress((void**)&p_cA,    g_cA);
    cudaGetSymbolAddress((void**)&p_cH,    g_cH);
    cudaGetSymbolAddress((void**)&p_hs,    g_hs);

    cudaMemcpyAsync(xbuf, x_in, (size_t)NTOK * D_MODEL * sizeof(float),
                    cudaMemcpyDeviceToDevice);

    const int EW_THREADS = 256;
    const int EW_BLOCKS  = (NTOK * D_INNER + EW_THREADS - 1) / EW_THREADS;
    const int SCAN_BLOCKS = BATCH * NCHUNK * 32;

    for (int layer = 0; layer < DEPTH; layer++) {
        const float* l_lnw  = ln_w + layer * D_MODEL;
        const float* l_lnb  = ln_b + layer * D_MODEL;
        const float* l_ipw  = ipw  + (size_t)layer * 2 * D_INNER * D_MODEL;
        const float* l_cw   = cw   + (size_t)layer * D_INNER * D_CONV;
        const float* l_cb   = cb   + (size_t)layer * D_INNER;
        const float* l_xpw  = xpw  + (size_t)layer * DBL_COLS * D_INNER;
        const float* l_dpw  = dpw  + (size_t)layer * D_INNER * DT_RANK;
        const float* l_dpb  = dpb  + (size_t)layer * D_INNER;
        const float* l_alog = alog + (size_t)layer * D_INNER * D_STATE;
        const float* l_dpar = dpar + (size_t)layer * D_INNER;
        const float* l_opw  = opw  + (size_t)layer * D_MODEL * D_INNER;

        // 1. LayerNorm
        ln_kernel<<<NTOK, D_MODEL>>>(xbuf, l_lnw, l_lnb, p_h);

        // 2. in_proj
        gemm_tf32<0><<<dim3((2 * D_INNER + 63) / 64, NTOK / 128), 256>>>(
            p_h, D_MODEL, l_ipw, D_MODEL, p_xz, 2 * D_INNER,
            2 * D_INNER, D_MODEL, nullptr);

        // 3. depthwise conv + silu
        conv_silu_kernel<<<EW_BLOCKS, EW_THREADS>>>(p_xz, l_cw, l_cb, p_xc);

        // 4. x_proj
        gemm_tf32<0><<<dim3(1, NTOK / 128), 256>>>(
            p_xc, D_INNER, l_xpw, D_INNER, p_dbl, DBL_COLS,
            DBL_COLS, D_INNER, nullptr);

        // 5. delta
        gemm_tf32<1><<<dim3((D_INNER + 63) / 64, NTOK / 128), 256>>>(
            p_dbl, DBL_COLS, l_dpw, DT_RANK, p_delta, D_INNER,
            D_INNER, DT_RANK, l_dpb);

        // 6. chunked scan + fused gate
        scan_part1<<<SCAN_BLOCKS, 256>>>(p_delta, p_dbl, p_xc, l_alog, p_cA, p_cH);
        scan_part2<<<(BATCH * D_INNER * D_STATE + 255) / 256, 256>>>(p_cA, p_cH, p_hs);
        scan_part3<<<SCAN_BLOCKS, 256>>>(p_delta, p_dbl, p_xc, p_xz,
                                         l_alog, l_dpar, p_hs, p_y);

        // 7. out_proj + residual
        gemm_tf32<2><<<dim3((D_MODEL + 63) / 64, NTOK / 128), 256>>>(
            p_y, D_INNER, l_opw, D_INNER, xbuf, D_MODEL,
            D_MODEL, D_INNER, nullptr);
    }
}

// round 4
// speedup vs baseline: 5.0723x; 1.3916x over previous
#include <cuda_runtime.h>
#include <cuda_bf16.h>
#include <math.h>
#include <stdint.h>

// ---------------------------------------------------------------------------
#define D_MODEL   256
#define DEPTH     2
#define D_INNER   512
#define D_STATE   16
#define D_CONV    4
#define DT_RANK   16
#define BATCH     2
#define SEQLEN    2048
#define NTOK      (BATCH * SEQLEN)          // 4096
#define DBL_COLS  (DT_RANK + 2 * D_STATE)   // 48

#define NCHUNK    32
#define CLEN      (SEQLEN / NCHUNK)         // 64
#define XP_SK     4                          // x_proj split-K

// ---------------------------------------------------------------------------
// Scratch
// ---------------------------------------------------------------------------
__device__ float g_h    [NTOK * D_MODEL];
__device__ float g_xz   [NTOK * 2 * D_INNER];
__device__ float g_xc   [NTOK * D_INNER];
__device__ float g_dbl  [NTOK * DBL_COLS];
__device__ float g_part [XP_SK * NTOK * DBL_COLS];
__device__ float g_y    [NTOK * D_INNER];
__device__ float g_cA   [BATCH * NCHUNK * D_INNER * D_STATE];
__device__ float g_cH   [BATCH * NCHUNK * D_INNER * D_STATE];
__device__ float g_hs   [BATCH * NCHUNK * D_INNER * D_STATE];

// ---------------------------------------------------------------------------
// cp.async helpers
// ---------------------------------------------------------------------------
__device__ __forceinline__ uint32_t smem_u32(const void* p) {
    uint32_t a;
    asm("{.reg .u64 t; cvta.to.shared.u64 t, %1; cvt.u32.u64 %0, t;}"
        : "=r"(a) : "l"(p));
    return a;
}
__device__ __forceinline__ void cp_async16(void* dst, const void* src) {
    asm volatile("cp.async.ca.shared.global [%0], [%1], 16;"
                 :: "r"(smem_u32(dst)), "l"(src));
}
__device__ __forceinline__ void cp_async16_z(void* dst, const void* src, bool ok) {
    int sz = ok ? 16 : 0;
    asm volatile("cp.async.ca.shared.global [%0], [%1], 16, %2;"
                 :: "r"(smem_u32(dst)), "l"(src), "r"(sz));
}
#define CP_COMMIT() asm volatile("cp.async.commit_group;")
#define CP_WAIT0()  asm volatile("cp.async.wait_group 0;")

// ---------------------------------------------------------------------------
// LayerNorm
// ---------------------------------------------------------------------------
__global__ void ln_kernel(const float* __restrict__ x,
                          const float* __restrict__ w,
                          const float* __restrict__ b,
                          float* __restrict__ out)
{
    __shared__ float s_sum[8], s_sq[8];
    int t = blockIdx.x;
    int d = threadIdx.x;
    float v = x[t * D_MODEL + d];

    float s = v, q = v * v;
    #pragma unroll
    for (int o = 16; o > 0; o >>= 1) {
        s += __shfl_xor_sync(0xffffffffu, s, o);
        q += __shfl_xor_sync(0xffffffffu, q, o);
    }
    int warp = threadIdx.x >> 5;
    if ((threadIdx.x & 31) == 0) { s_sum[warp] = s; s_sq[warp] = q; }
    __syncthreads();
    if (threadIdx.x < 8) { s = s_sum[threadIdx.x]; q = s_sq[threadIdx.x]; }
    else                 { s = 0.f; q = 0.f; }
    if (warp == 0) {
        #pragma unroll
        for (int o = 4; o > 0; o >>= 1) {
            s += __shfl_xor_sync(0xffffffffu, s, o);
            q += __shfl_xor_sync(0xffffffffu, q, o);
        }
        if (threadIdx.x == 0) { s_sum[0] = s; s_sq[0] = q; }
    }
    __syncthreads();
    float mu  = s_sum[0] * (1.f / D_MODEL);
    float var = s_sq[0] * (1.f / D_MODEL) - mu * mu;
    float inv = rsqrtf(var + 1e-5f);
    out[t * D_MODEL + d] = (v - mu) * inv * w[d] + b[d];
}

// ---------------------------------------------------------------------------
// tf32 tensor-core GEMM, cp.async double-buffered.
// C[M,N] = A[M,K] @ W[N,K]^T. MODE 0: store | MODE 2: C += acc.
// blockIdx.z = split-K slice: A += z*K (K = per-slice len), C += z*csplit.
// Raw fp32 bits fed to tf32 mma (truncate rounding).
// ---------------------------------------------------------------------------
template <int MODE>
__global__ __launch_bounds__(256)
void gemm_tf32(const float* __restrict__ A, int lda,
               const float* __restrict__ W, int ldw,
               float*       __restrict__ C, int ldc,
               int N, int K, size_t csplit)
{
    const int BM = 128, BN = 64, BK = 16, LDS = 20;
    __shared__ uint32_t As[2][BM * LDS];
    __shared__ uint32_t Bs[2][BN * LDS];

    A += (size_t)blockIdx.z * K;
    C += (size_t)blockIdx.z * csplit;

    int tid  = threadIdx.x;
    int lane = tid & 31;
    int warp = tid >> 5;
    int m0 = blockIdx.y * BM;
    int n0 = blockIdx.x * BN;
    int wm = (warp >> 1) * 32;
    int wn = (warp & 1) * 32;
    int gr = lane >> 2;
    int gc = lane & 3;

    float acc[2][4][4];
    #pragma unroll
    for (int mi = 0; mi < 2; mi++)
        #pragma unroll
        for (int ni = 0; ni < 4; ni++)
            #pragma unroll
            for (int e = 0; e < 4; e++) acc[mi][ni][e] = 0.f;

    int lrow = tid >> 2;
    int lcol = (tid & 3) * 4;

    auto issue = [&](int k0, int buf) {
        #pragma unroll
        for (int h = 0; h < 2; h++) {
            int r = lrow + h * 64;
            cp_async16(&As[buf][r * LDS + lcol],
                       &A[(size_t)(m0 + r) * lda + k0 + lcol]);
        }
        {
            int r = lrow;
            bool ok = (n0 + r) < N;
            const float* src = ok ? &W[(size_t)(n0 + r) * ldw + k0 + lcol] : W;
            cp_async16_z(&Bs[buf][r * LDS + lcol], src, ok);
        }
    };

    int nk = K / BK;
    issue(0, 0);
    CP_COMMIT();

    for (int i = 0; i < nk; i++) {
        CP_WAIT0();
        __syncthreads();
        if (i + 1 < nk) { issue((i + 1) * BK, (i + 1) & 1); CP_COMMIT(); }
        int buf = i & 1;

        #pragma unroll
        for (int ks = 0; ks < BK; ks += 8) {
            uint32_t a[2][4], b[4][2];
            #pragma unroll
            for (int mi = 0; mi < 2; mi++) {
                int rb = wm + mi * 16 + gr;
                a[mi][0] = As[buf][rb * LDS + ks + gc];
                a[mi][1] = As[buf][(rb + 8) * LDS + ks + gc];
                a[mi][2] = As[buf][rb * LDS + ks + gc + 4];
                a[mi][3] = As[buf][(rb + 8) * LDS + ks + gc + 4];
            }
            #pragma unroll
            for (int ni = 0; ni < 4; ni++) {
                int rb = wn + ni * 8 + gr;
                b[ni][0] = Bs[buf][rb * LDS + ks + gc];
                b[ni][1] = Bs[buf][rb * LDS + ks + gc + 4];
            }
            #pragma unroll
            for (int mi = 0; mi < 2; mi++)
                #pragma unroll
                for (int ni = 0; ni < 4; ni++)
                    asm volatile(
                        "mma.sync.aligned.m16n8k8.row.col.f32.tf32.tf32.f32 "
                        "{%0,%1,%2,%3}, {%4,%5,%6,%7}, {%8,%9}, {%0,%1,%2,%3};"
                        : "+f"(acc[mi][ni][0]), "+f"(acc[mi][ni][1]),
                          "+f"(acc[mi][ni][2]), "+f"(acc[mi][ni][3])
                        : "r"(a[mi][0]), "r"(a[mi][1]), "r"(a[mi][2]), "r"(a[mi][3]),
                          "r"(b[ni][0]), "r"(b[ni][1]));
        }
    }

    #pragma unroll
    for (int mi = 0; mi < 2; mi++) {
        #pragma unroll
        for (int ni = 0; ni < 4; ni++) {
            #pragma unroll
            for (int e = 0; e < 4; e++) {
                int row = m0 + wm + mi * 16 + gr + ((e >= 2) ? 8 : 0);
                int col = n0 + wn + ni * 8 + gc * 2 + (e & 1);
                if (col < N) {
                    float v = acc[mi][ni][e];
                    if (MODE == 2) v += C[(size_t)row * ldc + col];
                    C[(size_t)row * ldc + col] = v;
                }
            }
        }
    }
}

// ---------------------------------------------------------------------------
// Reduce x_proj split-K partials
// ---------------------------------------------------------------------------
__global__ void reduce_dbl(const float* __restrict__ part,
                           float* __restrict__ dbl)
{
    int i = blockIdx.x * 256 + threadIdx.x;
    if (i < NTOK * DBL_COLS) {
        float s = part[i];
        #pragma unroll
        for (int z = 1; z < XP_SK; z++)
            s += part[(size_t)z * NTOK * DBL_COLS + i];
        dbl[i] = s;
    }
}

// ---------------------------------------------------------------------------
// Depthwise causal conv (D_CONV=4) + SiLU
// ---------------------------------------------------------------------------
__global__ void conv_silu_kernel(const float* __restrict__ xz,
                                 const float* __restrict__ cw,
                                 const float* __restrict__ cb,
                                 float* __restrict__ xc)
{
    int idx = blockIdx.x * blockDim.x + threadIdx.x;
    if (idx >= NTOK * D_INNER) return;
    int d = idx & (D_INNER - 1);
    int t = idx >> 9;
    int l = t & (SEQLEN - 1);

    float acc = cb[d];
    #pragma unroll
    for (int k = 0; k < D_CONV; k++) {
        int ll = l - (D_CONV - 1) + k;
        if (ll >= 0)
            acc += xz[(size_t)(t - (D_CONV - 1) + k) * (2 * D_INNER) + d] * cw[d * D_CONV + k];
    }
    float sg = 1.f / (1.f + __expf(-acc));
    xc[idx] = acc * sg;
}

// ---------------------------------------------------------------------------
// Scan part 1: per-chunk a-product + end state, delta fused, smem-staged.
// Grid: BATCH*NCHUNK*32, block 256 = 16 d x 16 n.
// ---------------------------------------------------------------------------
__global__ __launch_bounds__(256)
void scan_part1(const float* __restrict__ dbl,
                const float* __restrict__ xc,
                const float* __restrict__ A_log,
                const float* __restrict__ dpw,
                const float* __restrict__ dpb,
                float* __restrict__ cA,
                float* __restrict__ cH)
{
    __shared__ float s_dt[CLEN * 16];
    __shared__ float s_B [CLEN * 16];
    __shared__ float s_xc[CLEN * 16];
    __shared__ float s_dl[CLEN * 16];
    __shared__ float s_pw[16 * 17];

    int dg = blockIdx.x & 31;
    int c  = (blockIdx.x >> 5) & (NCHUNK - 1);
    int b  = blockIdx.x >> 10;
    int tid = threadIdx.x;
    int n  = tid & 15;
    int dl = tid >> 4;
    int d  = dg * 16 + dl;
    int l0 = c * CLEN;

    const float* dbl_p = dbl + ((size_t)b * SEQLEN + l0) * DBL_COLS;
    const float* xc_p  = xc  + ((size_t)b * SEQLEN + l0) * D_INNER + dg * 16;

    for (int idx = tid; idx < CLEN * 32; idx += 256) {
        int l = idx >> 5, cc = idx & 31;
        float v = dbl_p[(size_t)l * DBL_COLS + cc];
        if (cc < 16) s_dt[l * 16 + cc] = v;
        else         s_B [l * 16 + (cc - 16)] = v;
    }
    for (int idx = tid; idx < CLEN * 16; idx += 256) {
        int l = idx >> 4, dd = idx & 15;
        s_xc[l * 16 + dd] = xc_p[(size_t)l * D_INNER + dd];
    }
    {
        int rr = tid >> 4, cc = tid & 15;
        s_pw[rr * 17 + cc] = dpw[(size_t)(dg * 16 + rr) * DT_RANK + cc];
    }
    __syncthreads();

    for (int idx = tid; idx < CLEN * 16; idx += 256) {
        int l = idx >> 4, dd = idx & 15;
        float acc = dpb[dg * 16 + dd];
        #pragma unroll
        for (int r = 0; r < 16; r++)
            acc += s_dt[l * 16 + r] * s_pw[dd * 17 + r];
        s_dl[l * 16 + dd] = (acc > 20.f) ? acc : log1pf(__expf(acc));
    }
    __syncthreads();

    float Adn = -__expf(A_log[d * D_STATE + n]);
    float h = 0.f, P = 1.f;
    #pragma unroll 8
    for (int l = 0; l < CLEN; l++) {
        float dv = s_dl[l * 16 + dl];
        float a  = __expf(dv * Adn);
        h = a * h + (dv * s_xc[l * 16 + dl]) * s_B[l * 16 + n];
        P *= a;
    }
    size_t o = (((size_t)b * NCHUNK + c) * D_INNER + d) * D_STATE + n;
    cA[o] = P;
    cH[o] = h;
}

// ---------------------------------------------------------------------------
// Scan part 2: sequential chunk combine (16K independent streams)
// ---------------------------------------------------------------------------
__global__ void scan_part2(const float* __restrict__ cA,
                           const float* __restrict__ cH,
                           float* __restrict__ hs)
{
    int idx = blockIdx.x * blockDim.x + threadIdx.x;
    if (idx >= BATCH * D_INNER * D_STATE) return;
    int b = idx / (D_INNER * D_STATE);
    int r = idx % (D_INNER * D_STATE);
    float h = 0.f;
    #pragma unroll
    for (int c = 0; c < NCHUNK; c++) {
        size_t o = ((size_t)(b * NCHUNK + c)) * (D_INNER * D_STATE) + r;
        hs[o] = h;
        h = cA[o] * h + cH[o];
    }
}

// ---------------------------------------------------------------------------
// Scan part 3: replay with true start state, reduce over n, fused gate.
// ---------------------------------------------------------------------------
__global__ __launch_bounds__(256)
void scan_part3(const float* __restrict__ dbl,
                const float* __restrict__ xc,
                const float* __restrict__ xz,
                const float* __restrict__ A_log,
                const float* __restrict__ dpw,
                const float* __restrict__ dpb,
                const float* __restrict__ Dp,
                const float* __restrict__ hs,
                float* __restrict__ y)
{
    __shared__ float s_dt[CLEN * 16];
    __shared__ float s_B [CLEN * 16];
    __shared__ float s_C [CLEN * 16];
    __shared__ float s_xc[CLEN * 16];
    __shared__ float s_dl[CLEN * 16];
    __shared__ float s_y [CLEN * 16];
    __shared__ float s_pw[16 * 17];

    int dg = blockIdx.x & 31;
    int c  = (blockIdx.x >> 5) & (NCHUNK - 1);
    int b  = blockIdx.x >> 10;
    int tid = threadIdx.x;
    int n  = tid & 15;
    int dl = tid >> 4;
    int d  = dg * 16 + dl;
    int l0 = c * CLEN;

    const float* dbl_p = dbl + ((size_t)b * SEQLEN + l0) * DBL_COLS;
    const float* xc_p  = xc  + ((size_t)b * SEQLEN + l0) * D_INNER + dg * 16;
    const float* z_p   = xz  + ((size_t)b * SEQLEN + l0) * 2 * D_INNER + D_INNER + dg * 16;
    float*       y_p   = y   + ((size_t)b * SEQLEN + l0) * D_INNER + dg * 16;

    for (int idx = tid; idx < CLEN * DBL_COLS; idx += 256) {
        int l = idx / DBL_COLS, cc = idx % DBL_COLS;
        float v = dbl_p[(size_t)l * DBL_COLS + cc];
        if      (cc < 16) s_dt[l * 16 + cc] = v;
        else if (cc < 32) s_B [l * 16 + (cc - 16)] = v;
        else              s_C [l * 16 + (cc - 32)] = v;
    }
    for (int idx = tid; idx < CLEN * 16; idx += 256) {
        int l = idx >> 4, dd = idx & 15;
        s_xc[l * 16 + dd] = xc_p[(size_t)l * D_INNER + dd];
    }
    {
        int rr = tid >> 4, cc = tid & 15;
        s_pw[rr * 17 + cc] = dpw[(size_t)(dg * 16 + rr) * DT_RANK + cc];
    }
    __syncthreads();

    for (int idx = tid; idx < CLEN * 16; idx += 256) {
        int l = idx >> 4, dd = idx & 15;
        float acc = dpb[dg * 16 + dd];
        #pragma unroll
        for (int r = 0; r < 16; r++)
            acc += s_dt[l * 16 + r] * s_pw[dd * 17 + r];
        s_dl[l * 16 + dd] = (acc > 20.f) ? acc : log1pf(__expf(acc));
    }
    __syncthreads();

    float Adn = -__expf(A_log[d * D_STATE + n]);
    float h = hs[(((size_t)b * NCHUNK + c) * D_INNER + d) * D_STATE + n];

    #pragma unroll 4
    for (int l = 0; l < CLEN; l++) {
        float dv = s_dl[l * 16 + dl];
        h = __expf(dv * Adn) * h + (dv * s_xc[l * 16 + dl]) * s_B[l * 16 + n];
        float p = h * s_C[l * 16 + n];
        p += __shfl_xor_sync(0xffffffffu, p, 8);
        p += __shfl_xor_sync(0xffffffffu, p, 4);
        p += __shfl_xor_sync(0xffffffffu, p, 2);
        p += __shfl_xor_sync(0xffffffffu, p, 1);
        if (n == 0) s_y[l * 16 + dl] = p;
    }
    __syncthreads();

    for (int idx = tid; idx < CLEN * 16; idx += 256) {
        int l = idx >> 4, dd = idx & 15;
        float z = z_p[(size_t)l * 2 * D_INNER + dd];
        float sz = z / (1.f + __expf(-z));
        y_p[(size_t)l * D_INNER + dd] =
            (s_y[l * 16 + dd] + s_xc[l * 16 + dd] * Dp[dg * 16 + dd]) * sz;
    }
}

// ---------------------------------------------------------------------------
// Launcher
// ---------------------------------------------------------------------------
extern "C" void kernel_launch(void* const* d_in, const int* in_sizes, int n_in,
                              void* d_out, int out_size)
{
    const float* x_in = (const float*)d_in[0];
    const float* ln_w = (const float*)d_in[1];
    const float* ln_b = (const float*)d_in[2];
    const float* ipw  = (const float*)d_in[3];
    const float* cw   = (const float*)d_in[4];
    const float* cb   = (const float*)d_in[5];
    const float* xpw  = (const float*)d_in[6];
    const float* dpw  = (const float*)d_in[7];
    const float* dpb  = (const float*)d_in[8];
    const float* alog = (const float*)d_in[9];
    const float* dpar = (const float*)d_in[10];
    const float* opw  = (const float*)d_in[11];
    float* xbuf = (float*)d_out;

    float *p_h, *p_xz, *p_xc, *p_dbl, *p_part, *p_y, *p_cA, *p_cH, *p_hs;
    cudaGetSymbolAddress((void**)&p_h,    g_h);
    cudaGetSymbolAddress((void**)&p_xz,   g_xz);
    cudaGetSymbolAddress((void**)&p_xc,   g_xc);
    cudaGetSymbolAddress((void**)&p_dbl,  g_dbl);
    cudaGetSymbolAddress((void**)&p_part, g_part);
    cudaGetSymbolAddress((void**)&p_y,    g_y);
    cudaGetSymbolAddress((void**)&p_cA,   g_cA);
    cudaGetSymbolAddress((void**)&p_cH,   g_cH);
    cudaGetSymbolAddress((void**)&p_hs,   g_hs);

    cudaMemcpyAsync(xbuf, x_in, (size_t)NTOK * D_MODEL * sizeof(float),
                    cudaMemcpyDeviceToDevice);

    const int EW_THREADS = 256;
    const int EW_BLOCKS  = (NTOK * D_INNER + EW_THREADS - 1) / EW_THREADS;
    const int SCAN_BLOCKS = BATCH * NCHUNK * 32;

    for (int layer = 0; layer < DEPTH; layer++) {
        const float* l_lnw  = ln_w + layer * D_MODEL;
        const float* l_lnb  = ln_b + layer * D_MODEL;
        const float* l_ipw  = ipw  + (size_t)layer * 2 * D_INNER * D_MODEL;
        const float* l_cw   = cw   + (size_t)layer * D_INNER * D_CONV;
        const float* l_cb   = cb   + (size_t)layer * D_INNER;
        const float* l_xpw  = xpw  + (size_t)layer * DBL_COLS * D_INNER;
        const float* l_dpw  = dpw  + (size_t)layer * D_INNER * DT_RANK;
        const float* l_dpb  = dpb  + (size_t)layer * D_INNER;
        const float* l_alog = alog + (size_t)layer * D_INNER * D_STATE;
        const float* l_dpar = dpar + (size_t)layer * D_INNER;
        const float* l_opw  = opw  + (size_t)layer * D_MODEL * D_INNER;

        // 1. LayerNorm
        ln_kernel<<<NTOK, D_MODEL>>>(xbuf, l_lnw, l_lnb, p_h);

        // 2. in_proj: [4096,1024] = h @ ipw^T
        gemm_tf32<0><<<dim3(16, NTOK / 128, 1), 256>>>(
            p_h, D_MODEL, l_ipw, D_MODEL, p_xz, 2 * D_INNER,
            2 * D_INNER, D_MODEL, 0);

        // 3. conv + silu
        conv_silu_kernel<<<EW_BLOCKS, EW_THREADS>>>(p_xz, l_cw, l_cb, p_xc);

        // 4. x_proj split-K=4: partials, then reduce
        gemm_tf32<0><<<dim3(1, NTOK / 128, XP_SK), 256>>>(
            p_xc, D_INNER, l_xpw, D_INNER, p_part, DBL_COLS,
            DBL_COLS, D_INNER / XP_SK, (size_t)NTOK * DBL_COLS);
        reduce_dbl<<<(NTOK * DBL_COLS + 255) / 256, 256>>>(p_part, p_dbl);

        // 5. chunked scan (delta fused) + gate
        scan_part1<<<SCAN_BLOCKS, 256>>>(p_dbl, p_xc, l_alog, l_dpw, l_dpb,
                                         p_cA, p_cH);
        scan_part2<<<(BATCH * D_INNER * D_STATE + 255) / 256, 256>>>(
            p_cA, p_cH, p_hs);
        scan_part3<<<SCAN_BLOCKS, 256>>>(p_dbl, p_xc, p_xz, l_alog, l_dpw,
                                         l_dpb, l_dpar, p_hs, p_y);

        // 6. out_proj + residual
        gemm_tf32<2><<<dim3(4, NTOK / 128, 1), 256>>>(
            p_y, D_INNER, l_opw, D_INNER, xbuf, D_MODEL,
            D_MODEL, D_INNER, 0);
    }
}